// round 15
// baseline (speedup 1.0000x reference)
#include <cuda_runtime.h>

#define N_NODES 100000
#define E_EDGES 400000
#define DN 64
#define DE 32
#define DH 64
#define DIN_E 160
#define DIN_N 128
#define TE 64
#define TN 64
#define NT 256
#define EB (E_EDGES / TE)               // 6250 (exact)
#define NB ((N_NODES + TN - 1) / TN)    // 1563
#define BSTR 68                          // 64 + 4 pad
#define NSTR 132                         // 128 + 4 pad
#define EASTR 36                         // ea tile stride (32 + 4 pad)

typedef unsigned long long u64;

// Scratch (no cudaMalloc allowed).
// slots: 0 = a<-aa(row), 1 = a<-ab(row), 2 = b<-ab(col), 3 = b<-bb(row)
__device__ float g_sum[4][N_NODES * DE];
__device__ float g_cnt[4][N_NODES];
// Precomputed per-node edge-layer1 partials.
// seg: 0=P0(xa,A0,+b) 1=Q0(xa,B0) 2=P1(xa,A1,+b) 3=Q1(xb,B1) 4=P2(xb,A2,+b) 5=Q2(xb,B2)
__device__ float g_PQ[6][N_NODES * DH];

// ---- packed fp32x2 helpers (sm_103a) ----
__device__ __forceinline__ u64 pack_dup(float x) {
    u64 r; asm("mov.b64 %0, {%1, %1};" : "=l"(r) : "r"(__float_as_uint(x))); return r;
}
__device__ __forceinline__ u64 pack_pair(float x, float y) {
    u64 r; asm("mov.b64 %0, {%1, %2};" : "=l"(r) : "r"(__float_as_uint(x)), "r"(__float_as_uint(y))); return r;
}
__device__ __forceinline__ float2 unpack(u64 v) {
    float2 f; asm("mov.b64 {%0, %1}, %2;" : "=f"(f.x), "=f"(f.y) : "l"(v)); return f;
}
__device__ __forceinline__ void fma2(u64& acc, u64 a, u64 b) {
    asm("fma.rn.f32x2 %0, %1, %2, %0;" : "+l"(acc) : "l"(a), "l"(b));
}
// fire-and-forget vector reduction (PTX ISA 8.1+, sm_90+)
__device__ __forceinline__ void red_v2(float* p, float x, float y) {
    asm volatile("red.global.add.v2.f32 [%0], {%1, %2};"
                 :: "l"(p), "f"(x), "f"(y) : "memory");
}
__device__ __forceinline__ void red_f1(float* p, float x) {
    asm volatile("red.global.add.f32 [%0], %1;" :: "l"(p), "f"(x) : "memory");
}
__device__ __forceinline__ void prefetch_l2(const void* p) {
    asm volatile("prefetch.global.L2 [%0];" :: "l"(p));
}

// Accumulate acc[4r][2 h-pairs] += buf[4 rows x KW] @ W[KW x 64].
template <int KW, int STR>
__device__ __forceinline__ void accum_l1(
    const float* buf, const float* __restrict__ W, int te, int th, u64 acc[4][2])
{
    const float* row = buf + (te * 4) * STR;
    #pragma unroll 4
    for (int k = 0; k < KW; k += 4) {
        float4 a0 = *(const float4*)(row + 0 * STR + k);
        float4 a1 = *(const float4*)(row + 1 * STR + k);
        float4 a2 = *(const float4*)(row + 2 * STR + k);
        float4 a3 = *(const float4*)(row + 3 * STR + k);
        const float* a[4] = {(const float*)&a0, (const float*)&a1,
                             (const float*)&a2, (const float*)&a3};
        #pragma unroll
        for (int kk = 0; kk < 4; kk++) {
            ulonglong2 wp = *((const ulonglong2*)(W + (k + kk) * DH) + th);
            #pragma unroll
            for (int i = 0; i < 4; i++) {
                u64 xx = pack_dup(a[i][kk]);
                fma2(acc[i][0], xx, wp.x);
                fma2(acc[i][1], xx, wp.y);
            }
        }
    }
}

// ---------------------------------------------------------------------------
// pre3: per block, 64 rows of one x matrix; stage tile once, run 3 weight
// blocks -> 3 g_PQ segments. Also zeroes a slice of g_sum/g_cnt.
// ---------------------------------------------------------------------------
__global__ void __launch_bounds__(NT, 4) pre3(
    const float* __restrict__ x_a, const float* __restrict__ x_b,
    const float* __restrict__ We1, const float* __restrict__ be1)
{
    __shared__ float buf[TN * BSTR];

    const int tid = threadIdx.x;
    const int which = blockIdx.x / NB;
    const int rblk = blockIdx.x - which * NB;
    const int r0 = rblk * TN;

    {
        const int nblocks = 2 * NB;
        float4* s4 = (float4*)&g_sum[0][0];
        const int total4 = 4 * N_NODES * DE / 4;
        const int per = (total4 + nblocks - 1) / nblocks;
        int base = blockIdx.x * per;
        int end = min(base + per, total4);
        for (int i = base + tid; i < end; i += NT)
            s4[i] = make_float4(0.f, 0.f, 0.f, 0.f);
        float* c = &g_cnt[0][0];
        const int ctot = 4 * N_NODES;
        const int cper = (ctot + nblocks - 1) / nblocks;
        int cbase = blockIdx.x * cper;
        int cend = min(cbase + cper, ctot);
        for (int i = cbase + tid; i < cend; i += NT)
            c[i] = 0.0f;
    }

    const float* x = which ? x_b : x_a;

    for (int it = tid; it < TN * 16; it += NT) {
        int n = it >> 4, cc = it & 15;
        int gn = r0 + n; if (gn >= N_NODES) gn = N_NODES - 1;
        *(float4*)(buf + n * BSTR + cc * 4) =
            __ldg((const float4*)(x + (size_t)gn * DN) + cc);
    }
    __syncthreads();

    const int th = tid & 15;
    const int te = tid >> 4;

    #pragma unroll
    for (int j = 0; j < 3; j++) {
        const int seg = which * 3 + j;
        const int type = seg >> 1;
        const int part = seg & 1;
        const float* W = We1 + type * DIN_E * DH + part * 64 * DH;
        float* outp = g_PQ[seg];

        u64 acc[4][2];
        if (part == 0) {
            float4 bv = __ldg((const float4*)(be1 + type * DH) + th);
            u64 p0 = pack_pair(bv.x, bv.y);
            u64 p1 = pack_pair(bv.z, bv.w);
            #pragma unroll
            for (int i = 0; i < 4; i++) { acc[i][0] = p0; acc[i][1] = p1; }
        } else {
            #pragma unroll
            for (int i = 0; i < 4; i++) { acc[i][0] = 0ull; acc[i][1] = 0ull; }
        }

        accum_l1<64, BSTR>(buf, W, te, th, acc);

        #pragma unroll
        for (int i = 0; i < 4; i++) {
            int gn = r0 + te * 4 + i;
            if (gn < N_NODES) {
                float2 o0 = unpack(acc[i][0]);
                float2 o1 = unpack(acc[i][1]);
                float4 ov; ov.x = o0.x; ov.y = o0.y; ov.z = o1.x; ov.w = o1.y;
                *(float4*)(outp + (size_t)gn * DH + th * 4) = ov;
            }
        }
    }
}

// ---------------------------------------------------------------------------
// Edge kernel (all 3 types merged): per block, 64 edges.
// sW2 staged in shared (R13 layer-2 loop); separate ea/h buffers drop the
// middle WAR sync. L2 prefetch of P/Q rows; vector red scatter.
// ---------------------------------------------------------------------------
__global__ void __launch_bounds__(NT, 4) edge_all(
    const int* __restrict__ ei_aa, const int* __restrict__ ei_ab,
    const int* __restrict__ ei_bb,
    const float* __restrict__ ea_aa, const float* __restrict__ ea_ab,
    const float* __restrict__ ea_bb,
    const float* __restrict__ We1,
    const float* __restrict__ We2, const float* __restrict__ be2,
    float* __restrict__ ne_base)
{
    __shared__ float eaBuf[TE * EASTR];   // 9.2 KB
    __shared__ float hBuf[TE * BSTR];     // 17.4 KB
    __shared__ float sW2[DH * DE];        // 8 KB
    __shared__ int sIdxR[TE];
    __shared__ int sIdxC[TE];

    const int tid = threadIdx.x;
    const int type = blockIdx.x / EB;
    const int eblk = blockIdx.x - type * EB;
    const int e0 = eblk * TE;

    const int* ei = (type == 0) ? ei_aa : (type == 1) ? ei_ab : ei_bb;
    const float* ea = (type == 0) ? ea_aa : (type == 1) ? ea_ab : ea_bb;
    const float* C  = We1 + type * DIN_E * DH + 128 * DH;   // [32 x 64]
    const float* W2 = We2 + type * DH * DE;
    const float* b2 = be2 + type * DE;
    const float* P = g_PQ[2 * type];
    const float* Q = g_PQ[2 * type + 1];
    float* ne = ne_base + (size_t)type * E_EDGES * DE;
    const int slot_row = (type == 0) ? 0 : (type == 1) ? 1 : 3;
    const bool has_col = (type == 1);

    for (int i = tid; i < DH * DE / 4; i += NT)
        ((float4*)sW2)[i] = ((const float4*)W2)[i];
    if (tid < TE) sIdxR[tid] = ei[e0 + tid];
    else if (tid < 2 * TE) sIdxC[tid - TE] = ei[E_EDGES + e0 + tid - TE];
    for (int it = tid; it < TE * 8; it += NT) {
        int e = it >> 3, c = it & 7;
        *(float4*)(eaBuf + e * EASTR + c * 4) =
            __ldg((const float4*)(ea + (size_t)(e0 + e) * DE) + c);
    }
    __syncthreads();

    // ---- L2 prefetch of P/Q rows: one 128B line per thread, overlapped with
    // the layer-1 GEMM below.
    {
        int e = tid >> 2;                 // 0..63
        int sel = (tid >> 1) & 1;         // P or Q
        int half = tid & 1;               // which 128B sector of the 256B row
        const float* base = sel ? (Q + (size_t)sIdxC[e] * DH)
                                : (P + (size_t)sIdxR[e] * DH);
        prefetch_l2(base + half * 32);
    }

    const int th = tid & 15;
    const int te = tid >> 4;

    u64 acc[4][2];
    #pragma unroll
    for (int i = 0; i < 4; i++) { acc[i][0] = 0ull; acc[i][1] = 0ull; }
    accum_l1<32, EASTR>(eaBuf, C, te, th, acc);

    // h = relu(acc + P[src] + Q[dst]) -> hBuf (separate buffer, no WAR sync)
    #pragma unroll
    for (int i = 0; i < 4; i++) {
        int e = te * 4 + i;
        float4 p = __ldg((const float4*)(P + (size_t)sIdxR[e] * DH) + th);
        float4 q = __ldg((const float4*)(Q + (size_t)sIdxC[e] * DH) + th);
        float2 a0 = unpack(acc[i][0]);
        float2 a1 = unpack(acc[i][1]);
        float4 h;
        h.x = fmaxf(a0.x + p.x + q.x, 0.f);
        h.y = fmaxf(a0.y + p.y + q.y, 0.f);
        h.z = fmaxf(a1.x + p.z + q.z, 0.f);
        h.w = fmaxf(a1.y + p.w + q.w, 0.f);
        *(float4*)(hBuf + e * BSTR + th * 4) = h;
    }
    __syncthreads();

    u64 acc2[4];
    {
        float2 b2v = __ldg((const float2*)b2 + th);
        u64 p = pack_pair(b2v.x, b2v.y);
        #pragma unroll
        for (int i = 0; i < 4; i++) acc2[i] = p;
    }
    const float* hRow = hBuf + (te * 4) * BSTR;
    #pragma unroll 4
    for (int k = 0; k < DH; k += 4) {
        float4 a0 = *(const float4*)(hRow + 0 * BSTR + k);
        float4 a1 = *(const float4*)(hRow + 1 * BSTR + k);
        float4 a2 = *(const float4*)(hRow + 2 * BSTR + k);
        float4 a3 = *(const float4*)(hRow + 3 * BSTR + k);
        const float* a[4] = {(const float*)&a0, (const float*)&a1,
                             (const float*)&a2, (const float*)&a3};
        #pragma unroll
        for (int kk = 0; kk < 4; kk++) {
            u64 w = *((const u64*)(sW2 + (k + kk) * DE) + th);
            #pragma unroll
            for (int i = 0; i < 4; i++)
                fma2(acc2[i], pack_dup(a[i][kk]), w);
        }
    }

    // ---- write ne + vector red scatter ----
    float* sum_row = g_sum[slot_row];
    float* cnt_row = g_cnt[slot_row];
    float* sum_col = has_col ? g_sum[2] : nullptr;
    float* cnt_col = has_col ? g_cnt[2] : nullptr;
    #pragma unroll
    for (int i = 0; i < 4; i++) {
        int e = te * 4 + i;
        int ge = e0 + e;
        float2 v = unpack(acc2[i]);
        *(float2*)(ne + (size_t)ge * DE + th * 2) = v;
        int r = sIdxR[e];
        red_v2(sum_row + (size_t)r * DE + th * 2, v.x, v.y);
        if (has_col) {
            int c = sIdxC[e];
            red_v2(sum_col + (size_t)c * DE + th * 2, v.x, v.y);
        }
        if (th == 0) {
            red_f1(cnt_row + r, 1.0f);
            if (has_col) red_f1(cnt_col + sIdxC[e], 1.0f);
        }
    }
}

// ---------------------------------------------------------------------------
// Node kernel (both types merged): per block, 64 nodes.
// ---------------------------------------------------------------------------
__global__ void __launch_bounds__(NT, 4) node_all(
    const float* __restrict__ x_a, const float* __restrict__ x_b,
    const float* __restrict__ Wn1, const float* __restrict__ bn1,
    const float* __restrict__ Wn2, const float* __restrict__ bn2,
    float* __restrict__ out)
{
    __shared__ float buf[TN * NSTR];

    const int tid = threadIdx.x;
    const int type = blockIdx.x / NB;
    const int nblk = blockIdx.x - type * NB;
    const int n0 = nblk * TN;

    const float* x = type ? x_b : x_a;
    const float* sum1 = g_sum[type ? 2 : 0];
    const float* cnt1 = g_cnt[type ? 2 : 0];
    const float* sum2 = g_sum[type ? 3 : 1];
    const float* cnt2 = g_cnt[type ? 3 : 1];
    const float* W1 = Wn1 + type * DIN_N * DH;
    const float* b1 = bn1 + type * DH;
    const float* W2 = Wn2 + type * DH * DN;
    const float* b2 = bn2 + type * DN;
    float* o = out + (size_t)type * N_NODES * DN;

    for (int it = tid; it < TN * 32; it += NT) {
        int n = it >> 5, c4 = it & 31;
        int gn = n0 + n;
        float4 v = make_float4(0.f, 0.f, 0.f, 0.f);
        if (gn < N_NODES) {
            if (c4 < 16) {
                v = __ldg((const float4*)(x + (size_t)gn * DN) + c4);
            } else if (c4 < 24) {
                v = *((const float4*)(sum1 + (size_t)gn * DE) + (c4 - 16));
                float rc = 1.0f / fmaxf(cnt1[gn], 1.0f);
                v.x *= rc; v.y *= rc; v.z *= rc; v.w *= rc;
            } else {
                v = *((const float4*)(sum2 + (size_t)gn * DE) + (c4 - 24));
                float rc = 1.0f / fmaxf(cnt2[gn], 1.0f);
                v.x *= rc; v.y *= rc; v.z *= rc; v.w *= rc;
            }
        }
        *(float4*)(buf + n * NSTR + c4 * 4) = v;
    }
    __syncthreads();

    const int th = tid & 15;
    const int te = tid >> 4;

    u64 acc[4][2];
    {
        float4 bv = __ldg((const float4*)b1 + th);
        u64 p0 = pack_pair(bv.x, bv.y);
        u64 p1 = pack_pair(bv.z, bv.w);
        #pragma unroll
        for (int i = 0; i < 4; i++) { acc[i][0] = p0; acc[i][1] = p1; }
    }
    accum_l1<128, NSTR>(buf, W1, te, th, acc);
    __syncthreads();

    #pragma unroll
    for (int i = 0; i < 4; i++) {
        float2 h0 = unpack(acc[i][0]);
        float2 h1 = unpack(acc[i][1]);
        float4 h;
        h.x = fmaxf(h0.x, 0.f); h.y = fmaxf(h0.y, 0.f);
        h.z = fmaxf(h1.x, 0.f); h.w = fmaxf(h1.y, 0.f);
        *(float4*)(buf + (te * 4 + i) * BSTR + th * 4) = h;
    }
    __syncthreads();

    u64 acc2[4][2];
    {
        float4 bv = __ldg((const float4*)b2 + th);
        u64 p0 = pack_pair(bv.x, bv.y);
        u64 p1 = pack_pair(bv.z, bv.w);
        #pragma unroll
        for (int i = 0; i < 4; i++) { acc2[i][0] = p0; acc2[i][1] = p1; }
    }
    accum_l1<64, BSTR>(buf, W2, te, th, acc2);

    #pragma unroll
    for (int i = 0; i < 4; i++) {
        int gn = n0 + te * 4 + i;
        if (gn < N_NODES) {
            float2 o0 = unpack(acc2[i][0]);
            float2 o1 = unpack(acc2[i][1]);
            float4 ov; ov.x = o0.x; ov.y = o0.y; ov.z = o1.x; ov.w = o1.y;
            *(float4*)(o + (size_t)gn * DN + th * 4) = ov;
        }
    }
}

extern "C" void kernel_launch(void* const* d_in, const int* in_sizes, int n_in,
                              void* d_out, int out_size) {
    const float* x_a  = (const float*)d_in[0];
    const float* x_b  = (const float*)d_in[1];
    const int*   ei_aa = (const int*)d_in[2];
    const int*   ei_ab = (const int*)d_in[3];
    const int*   ei_bb = (const int*)d_in[4];
    const float* ea_aa = (const float*)d_in[5];
    const float* ea_ab = (const float*)d_in[6];
    const float* ea_bb = (const float*)d_in[7];
    const float* We1 = (const float*)d_in[8];
    const float* be1 = (const float*)d_in[9];
    const float* We2 = (const float*)d_in[10];
    const float* be2 = (const float*)d_in[11];
    const float* Wn1 = (const float*)d_in[12];
    const float* bn1 = (const float*)d_in[13];
    const float* Wn2 = (const float*)d_in[14];
    const float* bn2 = (const float*)d_in[15];

    float* out   = (float*)d_out;
    float* nx_a  = out;
    float* ne_base = out + 2 * (size_t)N_NODES * DN;   // ne_aa, ne_ab, ne_bb

    pre3<<<2 * NB, NT>>>(x_a, x_b, We1, be1);

    edge_all<<<3 * EB, NT>>>(ei_aa, ei_ab, ei_bb,
                             ea_aa, ea_ab, ea_bb,
                             We1, We2, be2, ne_base);

    node_all<<<2 * NB, NT>>>(x_a, x_b, Wn1, bn1, Wn2, bn2, nx_a);
}

// round 16
// speedup vs baseline: 1.0528x; 1.0528x over previous
#include <cuda_runtime.h>

#define N_NODES 100000
#define E_EDGES 400000
#define DN 64
#define DE 32
#define DH 64
#define DIN_E 160
#define DIN_N 128
#define TE 64
#define TN 64
#define NT 256
#define EB (E_EDGES / TE)               // 6250 (exact)
#define NB ((N_NODES + TN - 1) / TN)    // 1563
#define BSTR 68                          // 64 + 4 pad
#define NSTR 132                         // 128 + 4 pad

typedef unsigned long long u64;

// Scratch (no cudaMalloc allowed).
// slots: 0 = a<-aa(row), 1 = a<-ab(row), 2 = b<-ab(col), 3 = b<-bb(row)
__device__ float g_sum[4][N_NODES * DE];
__device__ float g_cnt[4][N_NODES];
// Precomputed per-node edge-layer1 partials.
// seg: 0=P0(xa,A0,+b) 1=Q0(xa,B0) 2=P1(xa,A1,+b) 3=Q1(xb,B1) 4=P2(xb,A2,+b) 5=Q2(xb,B2)
__device__ float g_PQ[6][N_NODES * DH];

// ---- packed fp32x2 helpers (sm_103a) ----
__device__ __forceinline__ u64 pack_dup(float x) {
    u64 r; asm("mov.b64 %0, {%1, %1};" : "=l"(r) : "r"(__float_as_uint(x))); return r;
}
__device__ __forceinline__ u64 pack_pair(float x, float y) {
    u64 r; asm("mov.b64 %0, {%1, %2};" : "=l"(r) : "r"(__float_as_uint(x)), "r"(__float_as_uint(y))); return r;
}
__device__ __forceinline__ float2 unpack(u64 v) {
    float2 f; asm("mov.b64 {%0, %1}, %2;" : "=f"(f.x), "=f"(f.y) : "l"(v)); return f;
}
__device__ __forceinline__ void fma2(u64& acc, u64 a, u64 b) {
    asm("fma.rn.f32x2 %0, %1, %2, %0;" : "+l"(acc) : "l"(a), "l"(b));
}
// fire-and-forget vector reduction (PTX ISA 8.1+, sm_90+)
__device__ __forceinline__ void red_v2(float* p, float x, float y) {
    asm volatile("red.global.add.v2.f32 [%0], {%1, %2};"
                 :: "l"(p), "f"(x), "f"(y) : "memory");
}
__device__ __forceinline__ void red_f1(float* p, float x) {
    asm volatile("red.global.add.f32 [%0], %1;" :: "l"(p), "f"(x) : "memory");
}
__device__ __forceinline__ void prefetch_l2(const void* p) {
    asm volatile("prefetch.global.L2 [%0];" :: "l"(p));
}

// Accumulate acc[4r][2 h-pairs] += buf[4 rows x KW] @ W[KW x 64].
template <int KW, int STR>
__device__ __forceinline__ void accum_l1(
    const float* buf, const float* __restrict__ W, int te, int th, u64 acc[4][2])
{
    const float* row = buf + (te * 4) * STR;
    #pragma unroll 4
    for (int k = 0; k < KW; k += 4) {
        float4 a0 = *(const float4*)(row + 0 * STR + k);
        float4 a1 = *(const float4*)(row + 1 * STR + k);
        float4 a2 = *(const float4*)(row + 2 * STR + k);
        float4 a3 = *(const float4*)(row + 3 * STR + k);
        const float* a[4] = {(const float*)&a0, (const float*)&a1,
                             (const float*)&a2, (const float*)&a3};
        #pragma unroll
        for (int kk = 0; kk < 4; kk++) {
            ulonglong2 wp = *((const ulonglong2*)(W + (k + kk) * DH) + th);
            #pragma unroll
            for (int i = 0; i < 4; i++) {
                u64 xx = pack_dup(a[i][kk]);
                fma2(acc[i][0], xx, wp.x);
                fma2(acc[i][1], xx, wp.y);
            }
        }
    }
}

// ---------------------------------------------------------------------------
// pre3: per block, 64 rows of one x matrix; stage tile once, run 3 weight
// blocks -> 3 g_PQ segments. Also zeroes a slice of g_sum/g_cnt.
// ---------------------------------------------------------------------------
__global__ void __launch_bounds__(NT, 4) pre3(
    const float* __restrict__ x_a, const float* __restrict__ x_b,
    const float* __restrict__ We1, const float* __restrict__ be1)
{
    __shared__ float buf[TN * BSTR];

    const int tid = threadIdx.x;
    const int which = blockIdx.x / NB;
    const int rblk = blockIdx.x - which * NB;
    const int r0 = rblk * TN;

    {
        const int nblocks = 2 * NB;
        float4* s4 = (float4*)&g_sum[0][0];
        const int total4 = 4 * N_NODES * DE / 4;
        const int per = (total4 + nblocks - 1) / nblocks;
        int base = blockIdx.x * per;
        int end = min(base + per, total4);
        for (int i = base + tid; i < end; i += NT)
            s4[i] = make_float4(0.f, 0.f, 0.f, 0.f);
        float* c = &g_cnt[0][0];
        const int ctot = 4 * N_NODES;
        const int cper = (ctot + nblocks - 1) / nblocks;
        int cbase = blockIdx.x * cper;
        int cend = min(cbase + cper, ctot);
        for (int i = cbase + tid; i < cend; i += NT)
            c[i] = 0.0f;
    }

    const float* x = which ? x_b : x_a;

    for (int it = tid; it < TN * 16; it += NT) {
        int n = it >> 4, cc = it & 15;
        int gn = r0 + n; if (gn >= N_NODES) gn = N_NODES - 1;
        *(float4*)(buf + n * BSTR + cc * 4) =
            __ldg((const float4*)(x + (size_t)gn * DN) + cc);
    }
    __syncthreads();

    const int th = tid & 15;
    const int te = tid >> 4;

    #pragma unroll
    for (int j = 0; j < 3; j++) {
        const int seg = which * 3 + j;
        const int type = seg >> 1;
        const int part = seg & 1;
        const float* W = We1 + type * DIN_E * DH + part * 64 * DH;
        float* outp = g_PQ[seg];

        u64 acc[4][2];
        if (part == 0) {
            float4 bv = __ldg((const float4*)(be1 + type * DH) + th);
            u64 p0 = pack_pair(bv.x, bv.y);
            u64 p1 = pack_pair(bv.z, bv.w);
            #pragma unroll
            for (int i = 0; i < 4; i++) { acc[i][0] = p0; acc[i][1] = p1; }
        } else {
            #pragma unroll
            for (int i = 0; i < 4; i++) { acc[i][0] = 0ull; acc[i][1] = 0ull; }
        }

        accum_l1<64, BSTR>(buf, W, te, th, acc);

        #pragma unroll
        for (int i = 0; i < 4; i++) {
            int gn = r0 + te * 4 + i;
            if (gn < N_NODES) {
                float2 o0 = unpack(acc[i][0]);
                float2 o1 = unpack(acc[i][1]);
                float4 ov; ov.x = o0.x; ov.y = o0.y; ov.z = o1.x; ov.w = o1.y;
                *(float4*)(outp + (size_t)gn * DH + th * 4) = ov;
            }
        }
    }
}

// ---------------------------------------------------------------------------
// Edge kernel (all 3 types merged): per block, 64 edges.
// L2-prefetch P/Q rows before layer-1 GEMM so the mid-kernel gathers hit L2.
// ---------------------------------------------------------------------------
__global__ void __launch_bounds__(NT, 4) edge_all(
    const int* __restrict__ ei_aa, const int* __restrict__ ei_ab,
    const int* __restrict__ ei_bb,
    const float* __restrict__ ea_aa, const float* __restrict__ ea_ab,
    const float* __restrict__ ea_bb,
    const float* __restrict__ We1,
    const float* __restrict__ We2, const float* __restrict__ be2,
    float* __restrict__ ne_base)
{
    __shared__ float buf[TE * BSTR];   // ea tile then hidden
    __shared__ float sW2[DH * DE];
    __shared__ int sIdxR[TE];
    __shared__ int sIdxC[TE];

    const int tid = threadIdx.x;
    const int type = blockIdx.x / EB;
    const int eblk = blockIdx.x - type * EB;
    const int e0 = eblk * TE;

    const int* ei = (type == 0) ? ei_aa : (type == 1) ? ei_ab : ei_bb;
    const float* ea = (type == 0) ? ea_aa : (type == 1) ? ea_ab : ea_bb;
    const float* C  = We1 + type * DIN_E * DH + 128 * DH;   // [32 x 64]
    const float* W2 = We2 + type * DH * DE;
    const float* b2 = be2 + type * DE;
    const float* P = g_PQ[2 * type];
    const float* Q = g_PQ[2 * type + 1];
    float* ne = ne_base + (size_t)type * E_EDGES * DE;
    const int slot_row = (type == 0) ? 0 : (type == 1) ? 1 : 3;
    const bool has_col = (type == 1);

    for (int i = tid; i < DH * DE / 4; i += NT)
        ((float4*)sW2)[i] = ((const float4*)W2)[i];
    if (tid < TE) sIdxR[tid] = ei[e0 + tid];
    else if (tid < 2 * TE) sIdxC[tid - TE] = ei[E_EDGES + e0 + tid - TE];
    for (int it = tid; it < TE * 8; it += NT) {
        int e = it >> 3, c = it & 7;
        *(float4*)(buf + e * BSTR + c * 4) =
            __ldg((const float4*)(ea + (size_t)(e0 + e) * DE) + c);
    }
    __syncthreads();

    // ---- L2 prefetch of P/Q rows: 64 edges x 2 rows x 2 x 128B = 256 lines,
    // exactly one per thread; overlapped with the layer-1 GEMM below.
    {
        int e = tid >> 2;                 // 0..63
        int sel = (tid >> 1) & 1;         // P or Q
        int half = tid & 1;               // which 128B sector of the 256B row
        const float* base = sel ? (Q + (size_t)sIdxC[e] * DH)
                                : (P + (size_t)sIdxR[e] * DH);
        prefetch_l2(base + half * 32);
    }

    const int th = tid & 15;
    const int te = tid >> 4;

    u64 acc[4][2];
    #pragma unroll
    for (int i = 0; i < 4; i++) { acc[i][0] = 0ull; acc[i][1] = 0ull; }
    accum_l1<32, BSTR>(buf, C, te, th, acc);

    float4 hv[4];
    #pragma unroll
    for (int i = 0; i < 4; i++) {
        int e = te * 4 + i;
        float4 p = __ldg((const float4*)(P + (size_t)sIdxR[e] * DH) + th);
        float4 q = __ldg((const float4*)(Q + (size_t)sIdxC[e] * DH) + th);
        float2 a0 = unpack(acc[i][0]);
        float2 a1 = unpack(acc[i][1]);
        hv[i].x = fmaxf(a0.x + p.x + q.x, 0.f);
        hv[i].y = fmaxf(a0.y + p.y + q.y, 0.f);
        hv[i].z = fmaxf(a1.x + p.z + q.z, 0.f);
        hv[i].w = fmaxf(a1.y + p.w + q.w, 0.f);
    }
    __syncthreads();
    #pragma unroll
    for (int i = 0; i < 4; i++)
        *(float4*)(buf + (te * 4 + i) * BSTR + th * 4) = hv[i];
    __syncthreads();

    u64 acc2[4];
    {
        float2 b2v = __ldg((const float2*)b2 + th);
        u64 p = pack_pair(b2v.x, b2v.y);
        #pragma unroll
        for (int i = 0; i < 4; i++) acc2[i] = p;
    }
    const float* hRow = buf + (te * 4) * BSTR;
    #pragma unroll 4
    for (int k = 0; k < DH; k += 4) {
        float4 a0 = *(const float4*)(hRow + 0 * BSTR + k);
        float4 a1 = *(const float4*)(hRow + 1 * BSTR + k);
        float4 a2 = *(const float4*)(hRow + 2 * BSTR + k);
        float4 a3 = *(const float4*)(hRow + 3 * BSTR + k);
        const float* a[4] = {(const float*)&a0, (const float*)&a1,
                             (const float*)&a2, (const float*)&a3};
        #pragma unroll
        for (int kk = 0; kk < 4; kk++) {
            u64 w = *((const u64*)(sW2 + (k + kk) * DE) + th);
            #pragma unroll
            for (int i = 0; i < 4; i++)
                fma2(acc2[i], pack_dup(a[i][kk]), w);
        }
    }

    // ---- write ne + vector red scatter ----
    float* sum_row = g_sum[slot_row];
    float* cnt_row = g_cnt[slot_row];
    float* sum_col = has_col ? g_sum[2] : nullptr;
    float* cnt_col = has_col ? g_cnt[2] : nullptr;
    #pragma unroll
    for (int i = 0; i < 4; i++) {
        int e = te * 4 + i;
        int ge = e0 + e;
        float2 v = unpack(acc2[i]);
        *(float2*)(ne + (size_t)ge * DE + th * 2) = v;
        int r = sIdxR[e];
        red_v2(sum_row + (size_t)r * DE + th * 2, v.x, v.y);
        if (has_col) {
            int c = sIdxC[e];
            red_v2(sum_col + (size_t)c * DE + th * 2, v.x, v.y);
        }
        if (th == 0) {
            red_f1(cnt_row + r, 1.0f);
            if (has_col) red_f1(cnt_col + sIdxC[e], 1.0f);
        }
    }
}

// ---------------------------------------------------------------------------
// Node kernel (both types merged): per block, 64 nodes.
// ---------------------------------------------------------------------------
__global__ void __launch_bounds__(NT, 4) node_all(
    const float* __restrict__ x_a, const float* __restrict__ x_b,
    const float* __restrict__ Wn1, const float* __restrict__ bn1,
    const float* __restrict__ Wn2, const float* __restrict__ bn2,
    float* __restrict__ out)
{
    __shared__ float buf[TN * NSTR];

    const int tid = threadIdx.x;
    const int type = blockIdx.x / NB;
    const int nblk = blockIdx.x - type * NB;
    const int n0 = nblk * TN;

    const float* x = type ? x_b : x_a;
    const float* sum1 = g_sum[type ? 2 : 0];
    const float* cnt1 = g_cnt[type ? 2 : 0];
    const float* sum2 = g_sum[type ? 3 : 1];
    const float* cnt2 = g_cnt[type ? 3 : 1];
    const float* W1 = Wn1 + type * DIN_N * DH;
    const float* b1 = bn1 + type * DH;
    const float* W2 = Wn2 + type * DH * DN;
    const float* b2 = bn2 + type * DN;
    float* o = out + (size_t)type * N_NODES * DN;

    for (int it = tid; it < TN * 32; it += NT) {
        int n = it >> 5, c4 = it & 31;
        int gn = n0 + n;
        float4 v = make_float4(0.f, 0.f, 0.f, 0.f);
        if (gn < N_NODES) {
            if (c4 < 16) {
                v = __ldg((const float4*)(x + (size_t)gn * DN) + c4);
            } else if (c4 < 24) {
                v = *((const float4*)(sum1 + (size_t)gn * DE) + (c4 - 16));
                float rc = 1.0f / fmaxf(cnt1[gn], 1.0f);
                v.x *= rc; v.y *= rc; v.z *= rc; v.w *= rc;
            } else {
                v = *((const float4*)(sum2 + (size_t)gn * DE) + (c4 - 24));
                float rc = 1.0f / fmaxf(cnt2[gn], 1.0f);
                v.x *= rc; v.y *= rc; v.z *= rc; v.w *= rc;
            }
        }
        *(float4*)(buf + n * NSTR + c4 * 4) = v;
    }
    __syncthreads();

    const int th = tid & 15;
    const int te = tid >> 4;

    u64 acc[4][2];
    {
        float4 bv = __ldg((const float4*)b1 + th);
        u64 p0 = pack_pair(bv.x, bv.y);
        u64 p1 = pack_pair(bv.z, bv.w);
        #pragma unroll
        for (int i = 0; i < 4; i++) { acc[i][0] = p0; acc[i][1] = p1; }
    }
    accum_l1<128, NSTR>(buf, W1, te, th, acc);
    __syncthreads();

    #pragma unroll
    for (int i = 0; i < 4; i++) {
        float2 h0 = unpack(acc[i][0]);
        float2 h1 = unpack(acc[i][1]);
        float4 h;
        h.x = fmaxf(h0.x, 0.f); h.y = fmaxf(h0.y, 0.f);
        h.z = fmaxf(h1.x, 0.f); h.w = fmaxf(h1.y, 0.f);
        *(float4*)(buf + (te * 4 + i) * BSTR + th * 4) = h;
    }
    __syncthreads();

    u64 acc2[4][2];
    {
        float4 bv = __ldg((const float4*)b2 + th);
        u64 p0 = pack_pair(bv.x, bv.y);
        u64 p1 = pack_pair(bv.z, bv.w);
        #pragma unroll
        for (int i = 0; i < 4; i++) { acc2[i][0] = p0; acc2[i][1] = p1; }
    }
    accum_l1<64, BSTR>(buf, W2, te, th, acc2);

    #pragma unroll
    for (int i = 0; i < 4; i++) {
        int gn = n0 + te * 4 + i;
        if (gn < N_NODES) {
            float2 o0 = unpack(acc2[i][0]);
            float2 o1 = unpack(acc2[i][1]);
            float4 ov; ov.x = o0.x; ov.y = o0.y; ov.z = o1.x; ov.w = o1.y;
            *(float4*)(o + (size_t)gn * DN + th * 4) = ov;
        }
    }
}

extern "C" void kernel_launch(void* const* d_in, const int* in_sizes, int n_in,
                              void* d_out, int out_size) {
    const float* x_a  = (const float*)d_in[0];
    const float* x_b  = (const float*)d_in[1];
    const int*   ei_aa = (const int*)d_in[2];
    const int*   ei_ab = (const int*)d_in[3];
    const int*   ei_bb = (const int*)d_in[4];
    const float* ea_aa = (const float*)d_in[5];
    const float* ea_ab = (const float*)d_in[6];
    const float* ea_bb = (const float*)d_in[7];
    const float* We1 = (const float*)d_in[8];
    const float* be1 = (const float*)d_in[9];
    const float* We2 = (const float*)d_in[10];
    const float* be2 = (const float*)d_in[11];
    const float* Wn1 = (const float*)d_in[12];
    const float* bn1 = (const float*)d_in[13];
    const float* Wn2 = (const float*)d_in[14];
    const float* bn2 = (const float*)d_in[15];

    float* out   = (float*)d_out;
    float* nx_a  = out;
    float* ne_base = out + 2 * (size_t)N_NODES * DN;   // ne_aa, ne_ab, ne_bb

    pre3<<<2 * NB, NT>>>(x_a, x_b, We1, be1);

    edge_all<<<3 * EB, NT>>>(ei_aa, ei_ab, ei_bb,
                             ea_aa, ea_ab, ea_bb,
                             We1, We2, be2, ne_base);

    node_all<<<2 * NB, NT>>>(x_a, x_b, Wn1, bn1, Wn2, bn2, nx_a);
}

// round 17
// speedup vs baseline: 1.0534x; 1.0005x over previous
#include <cuda_runtime.h>

#define N_NODES 100000
#define E_EDGES 400000
#define DN 64
#define DE 32
#define DH 64
#define DIN_E 160
#define DIN_N 128
#define TE 64
#define TN 64
#define NT 256
#define EB (E_EDGES / TE)               // 6250 (exact)
#define NB ((N_NODES + TN - 1) / TN)    // 1563
#define BSTR 68                          // 64 + 4 pad
#define NSTR 132                         // 128 + 4 pad

typedef unsigned long long u64;

// Scratch (no cudaMalloc allowed).
// slots: 0 = a<-aa(row), 1 = a<-ab(row), 2 = b<-ab(col), 3 = b<-bb(row)
__device__ float g_sum[4][N_NODES * DE];
__device__ float g_cnt[4][N_NODES];
// Precomputed per-node edge-layer1 partials.
// seg: 0=P0(xa,A0,+b) 1=Q0(xa,B0) 2=P1(xa,A1,+b) 3=Q1(xb,B1) 4=P2(xb,A2,+b) 5=Q2(xb,B2)
__device__ float g_PQ[6][N_NODES * DH];

// ---- packed fp32x2 helpers (sm_103a) ----
__device__ __forceinline__ u64 pack_dup(float x) {
    u64 r; asm("mov.b64 %0, {%1, %1};" : "=l"(r) : "r"(__float_as_uint(x))); return r;
}
__device__ __forceinline__ u64 pack_pair(float x, float y) {
    u64 r; asm("mov.b64 %0, {%1, %2};" : "=l"(r) : "r"(__float_as_uint(x)), "r"(__float_as_uint(y))); return r;
}
__device__ __forceinline__ float2 unpack(u64 v) {
    float2 f; asm("mov.b64 {%0, %1}, %2;" : "=f"(f.x), "=f"(f.y) : "l"(v)); return f;
}
__device__ __forceinline__ void fma2(u64& acc, u64 a, u64 b) {
    asm("fma.rn.f32x2 %0, %1, %2, %0;" : "+l"(acc) : "l"(a), "l"(b));
}
// fire-and-forget vector reduction (PTX ISA 8.1+, sm_90+)
__device__ __forceinline__ void red_v2(float* p, float x, float y) {
    asm volatile("red.global.add.v2.f32 [%0], {%1, %2};"
                 :: "l"(p), "f"(x), "f"(y) : "memory");
}
__device__ __forceinline__ void red_f1(float* p, float x) {
    asm volatile("red.global.add.f32 [%0], %1;" :: "l"(p), "f"(x) : "memory");
}
__device__ __forceinline__ void prefetch_l2(const void* p) {
    asm volatile("prefetch.global.L2 [%0];" :: "l"(p));
}

// Accumulate acc[4r][2 h-pairs] += buf[4 rows x KW] @ W[KW x 64].
template <int KW, int STR>
__device__ __forceinline__ void accum_l1(
    const float* buf, const float* __restrict__ W, int te, int th, u64 acc[4][2])
{
    const float* row = buf + (te * 4) * STR;
    #pragma unroll 4
    for (int k = 0; k < KW; k += 4) {
        float4 a0 = *(const float4*)(row + 0 * STR + k);
        float4 a1 = *(const float4*)(row + 1 * STR + k);
        float4 a2 = *(const float4*)(row + 2 * STR + k);
        float4 a3 = *(const float4*)(row + 3 * STR + k);
        const float* a[4] = {(const float*)&a0, (const float*)&a1,
                             (const float*)&a2, (const float*)&a3};
        #pragma unroll
        for (int kk = 0; kk < 4; kk++) {
            ulonglong2 wp = *((const ulonglong2*)(W + (k + kk) * DH) + th);
            #pragma unroll
            for (int i = 0; i < 4; i++) {
                u64 xx = pack_dup(a[i][kk]);
                fma2(acc[i][0], xx, wp.x);
                fma2(acc[i][1], xx, wp.y);
            }
        }
    }
}

// ---------------------------------------------------------------------------
// pre3: per block, 64 rows of one x matrix; stage tile once, run 3 weight
// blocks -> 3 g_PQ segments. Also zeroes a slice of g_sum/g_cnt.
// ---------------------------------------------------------------------------
__global__ void __launch_bounds__(NT, 4) pre3(
    const float* __restrict__ x_a, const float* __restrict__ x_b,
    const float* __restrict__ We1, const float* __restrict__ be1)
{
    __shared__ float buf[TN * BSTR];

    const int tid = threadIdx.x;
    const int which = blockIdx.x / NB;
    const int rblk = blockIdx.x - which * NB;
    const int r0 = rblk * TN;

    {
        const int nblocks = 2 * NB;
        float4* s4 = (float4*)&g_sum[0][0];
        const int total4 = 4 * N_NODES * DE / 4;
        const int per = (total4 + nblocks - 1) / nblocks;
        int base = blockIdx.x * per;
        int end = min(base + per, total4);
        for (int i = base + tid; i < end; i += NT)
            s4[i] = make_float4(0.f, 0.f, 0.f, 0.f);
        float* c = &g_cnt[0][0];
        const int ctot = 4 * N_NODES;
        const int cper = (ctot + nblocks - 1) / nblocks;
        int cbase = blockIdx.x * cper;
        int cend = min(cbase + cper, ctot);
        for (int i = cbase + tid; i < cend; i += NT)
            c[i] = 0.0f;
    }

    const float* x = which ? x_b : x_a;

    for (int it = tid; it < TN * 16; it += NT) {
        int n = it >> 4, cc = it & 15;
        int gn = r0 + n; if (gn >= N_NODES) gn = N_NODES - 1;
        *(float4*)(buf + n * BSTR + cc * 4) =
            __ldg((const float4*)(x + (size_t)gn * DN) + cc);
    }
    __syncthreads();

    const int th = tid & 15;
    const int te = tid >> 4;

    #pragma unroll
    for (int j = 0; j < 3; j++) {
        const int seg = which * 3 + j;
        const int type = seg >> 1;
        const int part = seg & 1;
        const float* W = We1 + type * DIN_E * DH + part * 64 * DH;
        float* outp = g_PQ[seg];

        u64 acc[4][2];
        if (part == 0) {
            float4 bv = __ldg((const float4*)(be1 + type * DH) + th);
            u64 p0 = pack_pair(bv.x, bv.y);
            u64 p1 = pack_pair(bv.z, bv.w);
            #pragma unroll
            for (int i = 0; i < 4; i++) { acc[i][0] = p0; acc[i][1] = p1; }
        } else {
            #pragma unroll
            for (int i = 0; i < 4; i++) { acc[i][0] = 0ull; acc[i][1] = 0ull; }
        }

        accum_l1<64, BSTR>(buf, W, te, th, acc);

        #pragma unroll
        for (int i = 0; i < 4; i++) {
            int gn = r0 + te * 4 + i;
            if (gn < N_NODES) {
                float2 o0 = unpack(acc[i][0]);
                float2 o1 = unpack(acc[i][1]);
                float4 ov; ov.x = o0.x; ov.y = o0.y; ov.z = o1.x; ov.w = o1.y;
                *(float4*)(outp + (size_t)gn * DH + th * 4) = ov;
            }
        }
    }
}

// ---------------------------------------------------------------------------
// Edge kernel (all 3 types merged): per block, 64 edges.
// L2-prefetch P/Q rows before layer-1 GEMM so the mid-kernel gathers hit L2.
// ---------------------------------------------------------------------------
__global__ void __launch_bounds__(NT, 4) edge_all(
    const int* __restrict__ ei_aa, const int* __restrict__ ei_ab,
    const int* __restrict__ ei_bb,
    const float* __restrict__ ea_aa, const float* __restrict__ ea_ab,
    const float* __restrict__ ea_bb,
    const float* __restrict__ We1,
    const float* __restrict__ We2, const float* __restrict__ be2,
    float* __restrict__ ne_base)
{
    __shared__ float buf[TE * BSTR];   // ea tile then hidden
    __shared__ float sW2[DH * DE];
    __shared__ int sIdxR[TE];
    __shared__ int sIdxC[TE];

    const int tid = threadIdx.x;
    const int type = blockIdx.x / EB;
    const int eblk = blockIdx.x - type * EB;
    const int e0 = eblk * TE;

    const int* ei = (type == 0) ? ei_aa : (type == 1) ? ei_ab : ei_bb;
    const float* ea = (type == 0) ? ea_aa : (type == 1) ? ea_ab : ea_bb;
    const float* C  = We1 + type * DIN_E * DH + 128 * DH;   // [32 x 64]
    const float* W2 = We2 + type * DH * DE;
    const float* b2 = be2 + type * DE;
    const float* P = g_PQ[2 * type];
    const float* Q = g_PQ[2 * type + 1];
    float* ne = ne_base + (size_t)type * E_EDGES * DE;
    const int slot_row = (type == 0) ? 0 : (type == 1) ? 1 : 3;
    const bool has_col = (type == 1);

    for (int i = tid; i < DH * DE / 4; i += NT)
        ((float4*)sW2)[i] = ((const float4*)W2)[i];
    if (tid < TE) sIdxR[tid] = ei[e0 + tid];
    else if (tid < 2 * TE) sIdxC[tid - TE] = ei[E_EDGES + e0 + tid - TE];
    for (int it = tid; it < TE * 8; it += NT) {
        int e = it >> 3, c = it & 7;
        *(float4*)(buf + e * BSTR + c * 4) =
            __ldg((const float4*)(ea + (size_t)(e0 + e) * DE) + c);
    }
    __syncthreads();

    // ---- L2 prefetch of P/Q rows: 64 edges x 2 rows x 2 x 128B = 256 lines,
    // exactly one per thread; overlapped with the layer-1 GEMM below.
    {
        int e = tid >> 2;                 // 0..63
        int sel = (tid >> 1) & 1;         // P or Q
        int half = tid & 1;               // which 128B sector of the 256B row
        const float* base = sel ? (Q + (size_t)sIdxC[e] * DH)
                                : (P + (size_t)sIdxR[e] * DH);
        prefetch_l2(base + half * 32);
    }

    const int th = tid & 15;
    const int te = tid >> 4;

    u64 acc[4][2];
    #pragma unroll
    for (int i = 0; i < 4; i++) { acc[i][0] = 0ull; acc[i][1] = 0ull; }
    accum_l1<32, BSTR>(buf, C, te, th, acc);

    float4 hv[4];
    #pragma unroll
    for (int i = 0; i < 4; i++) {
        int e = te * 4 + i;
        float4 p = __ldg((const float4*)(P + (size_t)sIdxR[e] * DH) + th);
        float4 q = __ldg((const float4*)(Q + (size_t)sIdxC[e] * DH) + th);
        float2 a0 = unpack(acc[i][0]);
        float2 a1 = unpack(acc[i][1]);
        hv[i].x = fmaxf(a0.x + p.x + q.x, 0.f);
        hv[i].y = fmaxf(a0.y + p.y + q.y, 0.f);
        hv[i].z = fmaxf(a1.x + p.z + q.z, 0.f);
        hv[i].w = fmaxf(a1.y + p.w + q.w, 0.f);
    }
    __syncthreads();
    #pragma unroll
    for (int i = 0; i < 4; i++)
        *(float4*)(buf + (te * 4 + i) * BSTR + th * 4) = hv[i];
    __syncthreads();

    u64 acc2[4];
    {
        float2 b2v = __ldg((const float2*)b2 + th);
        u64 p = pack_pair(b2v.x, b2v.y);
        #pragma unroll
        for (int i = 0; i < 4; i++) acc2[i] = p;
    }
    const float* hRow = buf + (te * 4) * BSTR;
    #pragma unroll 4
    for (int k = 0; k < DH; k += 4) {
        float4 a0 = *(const float4*)(hRow + 0 * BSTR + k);
        float4 a1 = *(const float4*)(hRow + 1 * BSTR + k);
        float4 a2 = *(const float4*)(hRow + 2 * BSTR + k);
        float4 a3 = *(const float4*)(hRow + 3 * BSTR + k);
        const float* a[4] = {(const float*)&a0, (const float*)&a1,
                             (const float*)&a2, (const float*)&a3};
        #pragma unroll
        for (int kk = 0; kk < 4; kk++) {
            u64 w = *((const u64*)(sW2 + (k + kk) * DE) + th);
            #pragma unroll
            for (int i = 0; i < 4; i++)
                fma2(acc2[i], pack_dup(a[i][kk]), w);
        }
    }

    // ---- write ne + vector red scatter ----
    float* sum_row = g_sum[slot_row];
    float* cnt_row = g_cnt[slot_row];
    float* sum_col = has_col ? g_sum[2] : nullptr;
    float* cnt_col = has_col ? g_cnt[2] : nullptr;
    #pragma unroll
    for (int i = 0; i < 4; i++) {
        int e = te * 4 + i;
        int ge = e0 + e;
        float2 v = unpack(acc2[i]);
        *(float2*)(ne + (size_t)ge * DE + th * 2) = v;
        int r = sIdxR[e];
        red_v2(sum_row + (size_t)r * DE + th * 2, v.x, v.y);
        if (has_col) {
            int c = sIdxC[e];
            red_v2(sum_col + (size_t)c * DE + th * 2, v.x, v.y);
        }
        if (th == 0) {
            red_f1(cnt_row + r, 1.0f);
            if (has_col) red_f1(cnt_col + sIdxC[e], 1.0f);
        }
    }
}

// ---------------------------------------------------------------------------
// Node kernel (both types merged): per block, 64 nodes.
// ---------------------------------------------------------------------------
__global__ void __launch_bounds__(NT, 4) node_all(
    const float* __restrict__ x_a, const float* __restrict__ x_b,
    const float* __restrict__ Wn1, const float* __restrict__ bn1,
    const float* __restrict__ Wn2, const float* __restrict__ bn2,
    float* __restrict__ out)
{
    __shared__ float buf[TN * NSTR];

    const int tid = threadIdx.x;
    const int type = blockIdx.x / NB;
    const int nblk = blockIdx.x - type * NB;
    const int n0 = nblk * TN;

    const float* x = type ? x_b : x_a;
    const float* sum1 = g_sum[type ? 2 : 0];
    const float* cnt1 = g_cnt[type ? 2 : 0];
    const float* sum2 = g_sum[type ? 3 : 1];
    const float* cnt2 = g_cnt[type ? 3 : 1];
    const float* W1 = Wn1 + type * DIN_N * DH;
    const float* b1 = bn1 + type * DH;
    const float* W2 = Wn2 + type * DH * DN;
    const float* b2 = bn2 + type * DN;
    float* o = out + (size_t)type * N_NODES * DN;

    for (int it = tid; it < TN * 32; it += NT) {
        int n = it >> 5, c4 = it & 31;
        int gn = n0 + n;
        float4 v = make_float4(0.f, 0.f, 0.f, 0.f);
        if (gn < N_NODES) {
            if (c4 < 16) {
                v = __ldg((const float4*)(x + (size_t)gn * DN) + c4);
            } else if (c4 < 24) {
                v = *((const float4*)(sum1 + (size_t)gn * DE) + (c4 - 16));
                float rc = 1.0f / fmaxf(cnt1[gn], 1.0f);
                v.x *= rc; v.y *= rc; v.z *= rc; v.w *= rc;
            } else {
                v = *((const float4*)(sum2 + (size_t)gn * DE) + (c4 - 24));
                float rc = 1.0f / fmaxf(cnt2[gn], 1.0f);
                v.x *= rc; v.y *= rc; v.z *= rc; v.w *= rc;
            }
        }
        *(float4*)(buf + n * NSTR + c4 * 4) = v;
    }
    __syncthreads();

    const int th = tid & 15;
    const int te = tid >> 4;

    u64 acc[4][2];
    {
        float4 bv = __ldg((const float4*)b1 + th);
        u64 p0 = pack_pair(bv.x, bv.y);
        u64 p1 = pack_pair(bv.z, bv.w);
        #pragma unroll
        for (int i = 0; i < 4; i++) { acc[i][0] = p0; acc[i][1] = p1; }
    }
    accum_l1<128, NSTR>(buf, W1, te, th, acc);
    __syncthreads();

    #pragma unroll
    for (int i = 0; i < 4; i++) {
        float2 h0 = unpack(acc[i][0]);
        float2 h1 = unpack(acc[i][1]);
        float4 h;
        h.x = fmaxf(h0.x, 0.f); h.y = fmaxf(h0.y, 0.f);
        h.z = fmaxf(h1.x, 0.f); h.w = fmaxf(h1.y, 0.f);
        *(float4*)(buf + (te * 4 + i) * BSTR + th * 4) = h;
    }
    __syncthreads();

    u64 acc2[4][2];
    {
        float4 bv = __ldg((const float4*)b2 + th);
        u64 p0 = pack_pair(bv.x, bv.y);
        u64 p1 = pack_pair(bv.z, bv.w);
        #pragma unroll
        for (int i = 0; i < 4; i++) { acc2[i][0] = p0; acc2[i][1] = p1; }
    }
    accum_l1<64, BSTR>(buf, W2, te, th, acc2);

    #pragma unroll
    for (int i = 0; i < 4; i++) {
        int gn = n0 + te * 4 + i;
        if (gn < N_NODES) {
            float2 o0 = unpack(acc2[i][0]);
            float2 o1 = unpack(acc2[i][1]);
            float4 ov; ov.x = o0.x; ov.y = o0.y; ov.z = o1.x; ov.w = o1.y;
            *(float4*)(o + (size_t)gn * DN + th * 4) = ov;
        }
    }
}

extern "C" void kernel_launch(void* const* d_in, const int* in_sizes, int n_in,
                              void* d_out, int out_size) {
    const float* x_a  = (const float*)d_in[0];
    const float* x_b  = (const float*)d_in[1];
    const int*   ei_aa = (const int*)d_in[2];
    const int*   ei_ab = (const int*)d_in[3];
    const int*   ei_bb = (const int*)d_in[4];
    const float* ea_aa = (const float*)d_in[5];
    const float* ea_ab = (const float*)d_in[6];
    const float* ea_bb = (const float*)d_in[7];
    const float* We1 = (const float*)d_in[8];
    const float* be1 = (const float*)d_in[9];
    const float* We2 = (const float*)d_in[10];
    const float* be2 = (const float*)d_in[11];
    const float* Wn1 = (const float*)d_in[12];
    const float* bn1 = (const float*)d_in[13];
    const float* Wn2 = (const float*)d_in[14];
    const float* bn2 = (const float*)d_in[15];

    float* out   = (float*)d_out;
    float* nx_a  = out;
    float* ne_base = out + 2 * (size_t)N_NODES * DN;   // ne_aa, ne_ab, ne_bb

    pre3<<<2 * NB, NT>>>(x_a, x_b, We1, be1);

    edge_all<<<3 * EB, NT>>>(ei_aa, ei_ab, ei_bb,
                             ea_aa, ea_ab, ea_bb,
                             We1, We2, be2, ne_base);

    node_all<<<2 * NB, NT>>>(x_a, x_b, Wn1, bn1, Wn2, bn2, nx_a);
}